// round 1
// baseline (speedup 1.0000x reference)
#include <cuda_runtime.h>
#include <math.h>

#define HH 128
#define WW 128
#define NPIX (HH * WW)
#define NPTS 16384
#define KNN 16
#define FDIM 64

// Output layout (float32, concatenated in reference-return order):
//   depths [0, 16384)
//   colors [16384, 65536)          (H*W*3, channel-last)
//   feats  [65536, 1114112)        (H*W*64)
//   masks  [1114112, 1130496)      (bool -> 0.0/1.0)
#define OFF_DEPTH 0
#define OFF_COLOR (NPIX)
#define OFF_FEAT  (NPIX + NPIX * 3)
#define OFF_MASK  (NPIX + NPIX * 3 + NPIX * FDIM)

// ---- device scratch (no allocations allowed) ----
__device__ int   g_count[NPIX];
__device__ int   g_cursor[NPIX];
__device__ int   g_start[NPIX + 1];
__device__ float g_pu[NPTS];
__device__ float g_pv[NPTS];
__device__ float g_pz[NPTS];
__device__ int   g_pcell[NPTS];
__device__ float g_su[NPTS];
__device__ float g_sv[NPTS];
__device__ float g_sz[NPTS];
__device__ int   g_sidx[NPTS];
__device__ float g_wout[NPIX * KNN];
__device__ int   g_iout[NPIX * KNN];

__global__ void zero_kernel() {
    int i = blockIdx.x * blockDim.x + threadIdx.x;
    if (i < NPIX) { g_count[i] = 0; g_cursor[i] = 0; }
}

__global__ void project_count_kernel(const float* __restrict__ pts,
                                     const float* __restrict__ intr) {
    int i = blockIdx.x * blockDim.x + threadIdx.x;
    if (i >= NPTS) return;
    float x = pts[3 * i + 0];
    float y = pts[3 * i + 1];
    float z = pts[3 * i + 2];
    float fx = intr[0], cx = intr[2], fy = intr[4], cy = intr[5];
    bool valid = z > 1e-6f;
    float sz = valid ? z : 1.0f;
    // match reference op order: (x * fx) / z + cx
    float u = __fadd_rn(__fdiv_rn(__fmul_rn(x, fx), sz), cx);
    float v = __fadd_rn(__fdiv_rn(__fmul_rn(y, fy), sz), cy);
    if (!valid) { u = 1e9f; v = 1e9f; }
    g_pu[i] = u;
    g_pv[i] = v;
    g_pz[i] = z;
    int cell = -1;
    if (u > -2.0f && u < 130.0f && v > -2.0f && v < 130.0f) {
        int cu = (int)floorf(u);
        int cv = (int)floorf(v);
        cu = min(max(cu, 0), WW - 1);
        cv = min(max(cv, 0), HH - 1);
        cell = cv * WW + cu;
        atomicAdd(&g_count[cell], 1);
    }
    g_pcell[i] = cell;
}

__global__ void scan_kernel() {
    __shared__ int sums[1024];
    int t = threadIdx.x;
    int base = t * 16;
    int local[16];
    int s = 0;
#pragma unroll
    for (int k = 0; k < 16; ++k) { local[k] = s; s += g_count[base + k]; }
    sums[t] = s;
    __syncthreads();
    for (int off = 1; off < 1024; off <<= 1) {
        int v = 0;
        if (t >= off) v = sums[t - off];
        __syncthreads();
        if (t >= off) sums[t] += v;
        __syncthreads();
    }
    int prefix = (t > 0) ? sums[t - 1] : 0;
#pragma unroll
    for (int k = 0; k < 16; ++k) g_start[base + k] = prefix + local[k];
    if (t == 1023) g_start[NPIX] = sums[1023];
}

__global__ void scatter_kernel() {
    int i = blockIdx.x * blockDim.x + threadIdx.x;
    if (i >= NPTS) return;
    int cell = g_pcell[i];
    if (cell < 0) return;
    int pos = g_start[cell] + atomicAdd(&g_cursor[cell], 1);
    g_su[pos] = g_pu[i];
    g_sv[pos] = g_pv[i];
    g_sz[pos] = g_pz[i];
    g_sidx[pos] = i;
}

__global__ void knn_blend_kernel(const float* __restrict__ colors,
                                 float* __restrict__ out) {
    int p = blockIdx.x * blockDim.x + threadIdx.x;
    if (p >= NPIX) return;
    int pi = p >> 7;     // row
    int pj = p & 127;    // col
    float px = pj + 0.5f;
    float py = pi + 0.5f;

    float d2s[KNN];
    int   ids[KNN];
#pragma unroll
    for (int k = 0; k < KNN; ++k) { d2s[k] = 4.0f; ids[k] = -1; }

    int cv0 = max(pi - 2, 0), cv1 = min(pi + 2, HH - 1);
    int cu0 = max(pj - 2, 0), cu1 = min(pj + 2, WW - 1);

    for (int cv = cv0; cv <= cv1; ++cv) {
        int rowbase = cv * WW;
        int qs = g_start[rowbase + cu0];
        int qe = g_start[rowbase + cu1 + 1];
        for (int q = qs; q < qe; ++q) {
            float du = __fsub_rn(px, g_su[q]);
            float dv = __fsub_rn(py, g_sv[q]);
            float d2 = __fadd_rn(__fmul_rn(du, du), __fmul_rn(dv, dv));
            if (d2 < d2s[KNN - 1]) {
                d2s[KNN - 1] = d2;
                ids[KNN - 1] = q;
#pragma unroll
                for (int k = KNN - 1; k > 0; --k) {
                    if (d2s[k] < d2s[k - 1]) {
                        float td = d2s[k]; d2s[k] = d2s[k - 1]; d2s[k - 1] = td;
                        int   ti = ids[k]; ids[k] = ids[k - 1]; ids[k - 1] = ti;
                    }
                }
            }
        }
    }

    // weights: w = exp(-d2) for d2 < 4 (radius 2, sigma 1), else 0
    float w[KNN];
    float wsum = 0.0f;
    bool anyok = false;
#pragma unroll
    for (int k = 0; k < KNN; ++k) {
        bool ok = (ids[k] >= 0) && (d2s[k] < 4.0f);
        float wk = ok ? expf(-d2s[k]) : 0.0f;
        w[k] = wk;
        wsum += wk;
        anyok = anyok || ok;
    }
    float winv = 1.0f / (wsum + 1e-10f);

    float dsum = 0.0f;
    float c0 = 0.0f, c1 = 0.0f, c2 = 0.0f;
#pragma unroll
    for (int k = 0; k < KNN; ++k) {
        float wn = w[k] * winv;
        int q = ids[k];
        int oi = (q >= 0) ? g_sidx[q] : 0;
        float zk = (q >= 0) ? g_sz[q] : 0.0f;
        dsum += zk * wn;
        if (wn > 0.0f) {
            c0 += colors[3 * oi + 0] * wn;
            c1 += colors[3 * oi + 1] * wn;
            c2 += colors[3 * oi + 2] * wn;
        }
        g_wout[p * KNN + k] = (q >= 0) ? wn : 0.0f;
        g_iout[p * KNN + k] = (q >= 0) ? oi : 0;
    }

    out[OFF_DEPTH + p] = dsum;
    out[OFF_COLOR + 3 * p + 0] = c0;
    out[OFF_COLOR + 3 * p + 1] = c1;
    out[OFF_COLOR + 3 * p + 2] = c2;
    out[OFF_MASK + p] = anyok ? 1.0f : 0.0f;
}

__global__ void feat_blend_kernel(const float* __restrict__ feats,
                                  float* __restrict__ out) {
    int warps_per_block = blockDim.x >> 5;
    int p = blockIdx.x * warps_per_block + (threadIdx.x >> 5);
    int lane = threadIdx.x & 31;
    if (p >= NPIX) return;

    float a0 = 0.0f, a1 = 0.0f;
#pragma unroll
    for (int k = 0; k < KNN; ++k) {
        float wk = g_wout[p * KNN + k];   // broadcast load (warp-uniform)
        if (wk == 0.0f) break;            // weights descend with distance
        int id = g_iout[p * KNN + k];
        const float* f = feats + (size_t)id * FDIM;
        a0 += wk * f[lane];
        a1 += wk * f[lane + 32];
    }
    out[OFF_FEAT + (size_t)p * FDIM + lane] = a0;
    out[OFF_FEAT + (size_t)p * FDIM + lane + 32] = a1;
}

extern "C" void kernel_launch(void* const* d_in, const int* in_sizes, int n_in,
                              void* d_out, int out_size) {
    const float* pts    = (const float*)d_in[0];  // (N,3)
    const float* colors = (const float*)d_in[1];  // (N,3)
    const float* feats  = (const float*)d_in[2];  // (N,64)
    const float* intr   = (const float*)d_in[3];  // (3,3)
    float* out = (float*)d_out;

    zero_kernel<<<NPIX / 256, 256>>>();
    project_count_kernel<<<NPTS / 256, 256>>>(pts, intr);
    scan_kernel<<<1, 1024>>>();
    scatter_kernel<<<NPTS / 256, 256>>>();
    knn_blend_kernel<<<NPIX / 128, 128>>>(colors, out);
    feat_blend_kernel<<<NPIX / 8, 256>>>(feats, out);
}